// round 3
// baseline (speedup 1.0000x reference)
#include <cuda_runtime.h>

#define NB 256   // batch
#define NH 256   // hidden
#define NT 512   // time steps
#define NL 128   // latent
#define NCTA 128
#define NTHR 256

// smem layout (floats): weights 96*256 | W_ho 256 | h0 tile 256*64 | h1 tile 256*64
#define SM_W    0
#define SM_WO   (96*256)
#define SM_H0   (SM_WO + 256)
#define SM_H1   (SM_H0 + 256*64)
#define SM_FLOATS (SM_H1 + 256*64)
#define SMEM_BYTES (SM_FLOATS * 4)

// ping-pong h buffers, transposed [j][b]
__device__ float g_A[2][NH * NB];   // h0
__device__ float g_B[2][NH * NB];   // h1
__device__ unsigned g_arrive;       // zeroed by cudaMemsetAsync each launch

__device__ __forceinline__ float sigm(float x) {
    return __fdividef(1.0f, 1.0f + __expf(-x));
}
__device__ __forceinline__ float tanh_f(float x) {
    // exact identity tanh = 1 - 2/(e^{2x}+1); abs err ~1e-7, safe at +-inf
    float e = __expf(2.0f * x);
    return 1.0f - __fdividef(2.0f, e + 1.0f);
}

__device__ __forceinline__ void gridbar(unsigned target) {
    __syncthreads();
    if (threadIdx.x == 0) {
        __threadfence();
        atomicAdd(&g_arrive, 1u);
        while (*(volatile unsigned*)&g_arrive < target) { }
        __threadfence();
    }
    __syncthreads();
}

__global__ void __launch_bounds__(NTHR, 1)
lstm_persist_kernel(const float* __restrict__ latent,
                    const float* __restrict__ W_lh,  const float* __restrict__ b_lh,
                    const float* __restrict__ W_hh0, const float* __restrict__ b_ih0,
                    const float* __restrict__ b_hh0,
                    const float* __restrict__ W_ih1, const float* __restrict__ W_hh1,
                    const float* __restrict__ b_ih1, const float* __restrict__ b_hh1,
                    const float* __restrict__ W_ho,  const float* __restrict__ b_ho,
                    float* __restrict__ out)
{
    extern __shared__ float smem[];
    float* w_s  = smem + SM_W;
    float* wo_s = smem + SM_WO;
    float* h0_s = smem + SM_H0;
    float* h1_s = smem + SM_H1;

    const int tid  = threadIdx.x;
    const int warp = tid >> 5;
    const int lane = tid & 31;
    const int bt = blockIdx.x & 3;    // batch tile (64 batches)
    const int jt = blockIdx.x >> 2;   // hidden tile (8 units)
    const int j  = jt * 8 + warp;     // this thread's hidden unit
    const int b0base = bt * 64;

    // ---- one-time: stage the CTA's 96 weight rows into smem ----
    for (int idx = tid; idx < 96 * 64; idx += NTHR) {
        int r = idx >> 6, kq = idx & 63;                 // row, float4 within row
        int m = r >> 5, g = (r >> 3) & 3, jl = r & 7;    // matrix, gate, local j
        int grow = g * NH + jt * 8 + jl;
        const float* src = (m == 0) ? W_hh0 : (m == 1) ? W_ih1 : W_hh1;
        *(float4*)(w_s + r * 256 + kq * 4) = *(const float4*)(src + grow * NH + kq * 4);
    }
    if (tid < 256) wo_s[tid] = W_ho[tid];

    float bias0[4], bias1[4];
#pragma unroll
    for (int g = 0; g < 4; g++) {
        bias0[g] = b_ih0[g * NH + j] + b_hh0[g * NH + j];
        bias1[g] = b_ih1[g * NH + j] + b_hh1[g * NH + j];
    }
    const float bho = b_ho[0];

    // ---- init: h_init = latent @ W_lh.T + b_lh ; write to A[0] and B[0] ----
#pragma unroll
    for (int ch = 0; ch < 2; ch++) {
        int b = b0base + ch * 32 + lane;
        float acc = b_lh[j];
        for (int k = 0; k < NL; k += 4) {
            float4 lv = *(const float4*)(latent + b * NL + k);
            float4 wv = *(const float4*)(W_lh + j * NL + k);
            acc += lv.x * wv.x + lv.y * wv.y + lv.z * wv.z + lv.w * wv.w;
        }
        __stcg(&g_A[0][j * NB + b], acc);
        __stcg(&g_B[0][j * NB + b], acc);
    }
    float c0[2] = {0.f, 0.f}, c1[2] = {0.f, 0.f};

    unsigned bar = 0;
    gridbar(bar += NCTA);

    for (int tick = 1; tick <= NT + 2; tick++) {
        const int rb = (tick - 1) & 1;  // h0(tick-1) lives here; h1(tick-1) written here
        const int wb = tick & 1;        // h0(tick) written here; h1(tick-2) lives here

        // ---- stage h0(tick-1), h1(tick-2) tiles [k][b_local], L1-bypassed ----
        const float* Ap = g_A[rb];
        const float* Bp = g_B[wb];
        for (int idx = tid; idx < 4096; idx += NTHR) {
            int kk = idx >> 4, bq = idx & 15;
            float4 v0 = __ldcg((const float4*)(Ap + kk * NB + b0base + bq * 4));
            float4 v1 = __ldcg((const float4*)(Bp + kk * NB + b0base + bq * 4));
            *(float4*)(h0_s + kk * 64 + bq * 4) = v0;
            *(float4*)(h1_s + kk * 64 + bq * 4) = v1;
        }
        __syncthreads();

        // ---- fused GEMMs: z0 = W_hh0*h0 ; z1 = W_ih1*h0 + W_hh1*h1 ----
        float a0[2][4] = {{0.f,0.f,0.f,0.f},{0.f,0.f,0.f,0.f}};
        float a1[2][4] = {{0.f,0.f,0.f,0.f},{0.f,0.f,0.f,0.f}};
#pragma unroll 1
        for (int k4 = 0; k4 < 64; k4++) {
            float4 wv[12];
#pragma unroll
            for (int r = 0; r < 12; r++)   // r = mat*4 + gate
                wv[r] = *(const float4*)(w_s + ((r >> 2) * 32 + (r & 3) * 8 + warp) * 256 + k4 * 4);
#pragma unroll
            for (int ch = 0; ch < 2; ch++) {
                const int bl = ch * 32 + lane;
#pragma unroll
                for (int i = 0; i < 4; i++) {
                    float h0v = h0_s[(k4 * 4 + i) * 64 + bl];
                    float h1v = h1_s[(k4 * 4 + i) * 64 + bl];
#pragma unroll
                    for (int g = 0; g < 4; g++) {
                        a0[ch][g] += ((const float*)&wv[g])[i]     * h0v;
                        a1[ch][g] += ((const float*)&wv[4 + g])[i] * h0v;
                        a1[ch][g] += ((const float*)&wv[8 + g])[i] * h1v;
                    }
                }
            }
        }

        // ---- layer 0 state update: h0(tick) ----
        if (tick <= NT) {
            float* Aw = g_A[wb];
#pragma unroll
            for (int ch = 0; ch < 2; ch++) {
                int b = b0base + ch * 32 + lane;
                float zi = a0[ch][0] + bias0[0];
                float zf = a0[ch][1] + bias0[1];
                float zg = a0[ch][2] + bias0[2];
                float zo = a0[ch][3] + bias0[3];
                c0[ch] = sigm(zf) * c0[ch] + sigm(zi) * tanh_f(zg);
                float h = sigm(zo) * tanh_f(c0[ch]);
                __stcg(&Aw[j * NB + b], h);
            }
        }
        // ---- layer 1 state update: h1(tick-1) ----
        if (tick >= 2 && tick <= NT + 1) {
            float* Bw = g_B[rb];
#pragma unroll
            for (int ch = 0; ch < 2; ch++) {
                int b = b0base + ch * 32 + lane;
                float zi = a1[ch][0] + bias1[0];
                float zf = a1[ch][1] + bias1[1];
                float zg = a1[ch][2] + bias1[2];
                float zo = a1[ch][3] + bias1[3];
                c1[ch] = sigm(zf) * c1[ch] + sigm(zi) * tanh_f(zg);
                float h = sigm(zo) * tanh_f(c1[ch]);
                __stcg(&Bw[j * NB + b], h);
            }
        }
        // ---- output for step tick-2 (t = tick-3), from h1 tile in smem ----
        if (jt == 0 && tick >= 3) {
            int bl = tid >> 2, q = tid & 3;
            float v = 0.f;
            int kbase = q * 64;
#pragma unroll 8
            for (int k = 0; k < 64; k++)
                v += h1_s[(kbase + k) * 64 + bl] * wo_s[kbase + k];
            v += __shfl_xor_sync(0xffffffffu, v, 1);
            v += __shfl_xor_sync(0xffffffffu, v, 2);
            if (q == 0)
                out[(b0base + bl) * NT + (tick - 3)] = v + bho;
        }

        gridbar(bar += NCTA);
    }
}

extern "C" void kernel_launch(void* const* d_in, const int* in_sizes, int n_in,
                              void* d_out, int out_size)
{
    (void)in_sizes; (void)n_in; (void)out_size;
    cudaFuncSetAttribute(lstm_persist_kernel,
                         cudaFuncAttributeMaxDynamicSharedMemorySize, SMEM_BYTES);
    void* barp = nullptr;
    cudaGetSymbolAddress(&barp, g_arrive);
    cudaMemsetAsync(barp, 0, sizeof(unsigned));

    lstm_persist_kernel<<<NCTA, NTHR, SMEM_BYTES>>>(
        (const float*)d_in[0],   // latent
        (const float*)d_in[1],   // W_lh
        (const float*)d_in[2],   // b_lh
        // d_in[3] = W_ih0 (input is all-zero -> unused)
        (const float*)d_in[4],   // W_hh0
        (const float*)d_in[5],   // b_ih0
        (const float*)d_in[6],   // b_hh0
        (const float*)d_in[7],   // W_ih1
        (const float*)d_in[8],   // W_hh1
        (const float*)d_in[9],   // b_ih1
        (const float*)d_in[10],  // b_hh1
        (const float*)d_in[11],  // W_ho
        (const float*)d_in[12],  // b_ho
        (float*)d_out);
}

// round 4
// speedup vs baseline: 1.0513x; 1.0513x over previous
#include <cuda_runtime.h>

#define NB 256   // batch
#define NH 256   // hidden
#define NT 512   // time steps
#define NL 128   // latent
#define NCTA 128
#define NTHR 256

// smem: weights 96*256 floats (96KB) | h0 tile 64*64 float4 (64KB) | h1 tile (64KB)
#define SM_W_FLOATS   (96 * 256)
#define SM_H4         4096                 // 64 b * 64 k4 float4 per tile
#define SMEM_BYTES    ((SM_W_FLOATS + 8 * SM_H4) * 4)   // 24576*4 + 2*65536 = 229376

// ping-pong h buffers, layout [b][j]  (j = k for the consumer)
__device__ float g_A[2][NB * NH];   // h0
__device__ float g_B[2][NB * NH];   // h1
__device__ unsigned g_arrive;       // zeroed by cudaMemsetAsync each launch

__device__ __forceinline__ float sigm(float x) {
    return __fdividef(1.0f, 1.0f + __expf(-x));
}
__device__ __forceinline__ float tanh_f(float x) {
    float e = __expf(2.0f * x);
    return 1.0f - __fdividef(2.0f, e + 1.0f);
}

// packed f32x2 fma: d = a*b + c elementwise on two fp32 lanes of a 64-bit reg
__device__ __forceinline__ unsigned long long ffma2(unsigned long long a,
                                                    unsigned long long b,
                                                    unsigned long long c) {
    unsigned long long d;
    asm("fma.rn.f32x2 %0, %1, %2, %3;" : "=l"(d) : "l"(a), "l"(b), "l"(c));
    return d;
}
__device__ __forceinline__ float hsum2(unsigned long long p) {
    union { unsigned long long u; float2 f; } v;
    v.u = p;
    return v.f.x + v.f.y;
}

__device__ __forceinline__ void gridbar(unsigned target) {
    __syncthreads();
    if (threadIdx.x == 0) {
        __threadfence();
        atomicAdd(&g_arrive, 1u);
        while (*(volatile unsigned*)&g_arrive < target) { }
        __threadfence();
    }
    __syncthreads();
}

__global__ void __launch_bounds__(NTHR, 1)
lstm_persist_kernel(const float* __restrict__ latent,
                    const float* __restrict__ W_lh,  const float* __restrict__ b_lh,
                    const float* __restrict__ W_hh0, const float* __restrict__ b_ih0,
                    const float* __restrict__ b_hh0,
                    const float* __restrict__ W_ih1, const float* __restrict__ W_hh1,
                    const float* __restrict__ b_ih1, const float* __restrict__ b_hh1,
                    const float* __restrict__ W_ho,  const float* __restrict__ b_ho,
                    float* __restrict__ out)
{
    extern __shared__ float smem[];
    float*  w_s = smem;
    float4* h04 = (float4*)(smem + SM_W_FLOATS);
    float4* h14 = h04 + SM_H4;

    const int tid  = threadIdx.x;
    const int warp = tid >> 5;
    const int lane = tid & 31;
    const int bt = blockIdx.x & 3;    // batch tile (64 batches)
    const int jt = blockIdx.x >> 2;   // hidden tile (8 units)
    const int j  = jt * 8 + warp;     // this warp's hidden unit
    const int b0base = bt * 64;
    const int sw = lane & 7;          // smem swizzle key (same for lane and lane+32)

    // ---- one-time: stage this CTA's 96 weight rows (m: W_hh0, W_ih1, W_hh1) ----
    for (int idx = tid; idx < 96 * 64; idx += NTHR) {
        int r = idx >> 6, kq = idx & 63;
        int m = r >> 5, g = (r >> 3) & 3, jl = r & 7;
        int grow = g * NH + jt * 8 + jl;
        const float* src = (m == 0) ? W_hh0 : (m == 1) ? W_ih1 : W_hh1;
        *(float4*)(w_s + r * 256 + kq * 4) = *(const float4*)(src + grow * NH + kq * 4);
    }

    float bias0[4], bias1[4];
#pragma unroll
    for (int g = 0; g < 4; g++) {
        bias0[g] = b_ih0[g * NH + j] + b_hh0[g * NH + j];
        bias1[g] = b_ih1[g * NH + j] + b_hh1[g * NH + j];
    }
    const float bho = b_ho[0];

    // ---- init: h_init = latent @ W_lh.T + b_lh, written [b][j] to A[0], B[0] ----
#pragma unroll
    for (int ch = 0; ch < 2; ch++) {
        int b = b0base + ch * 32 + lane;
        float acc = b_lh[j];
        for (int k = 0; k < NL; k += 4) {
            float4 lv = *(const float4*)(latent + b * NL + k);
            float4 wv = *(const float4*)(W_lh + j * NL + k);
            acc += lv.x * wv.x + lv.y * wv.y + lv.z * wv.z + lv.w * wv.w;
        }
        __stcg(&g_A[0][b * NH + j], acc);
        __stcg(&g_B[0][b * NH + j], acc);
    }
    float c0[2] = {0.f, 0.f}, c1[2] = {0.f, 0.f};

    unsigned bar = 0;
    gridbar(bar += NCTA);

    const float4* wrow = ((const float4*)w_s) + warp * 64;  // this warp's row base

    for (int tick = 1; tick <= NT + 2; tick++) {
        const int rb = (tick - 1) & 1;  // h0(tick-1) here; h1(tick-1) written here
        const int wb = tick & 1;        // h0(tick) written here; h1(tick-2) here

        // ---- stage h0(tick-1) and h1(tick-2) as [b][k] tiles, XOR-swizzled ----
        {
            const float* Ap = g_A[rb];
            const float* Bp = g_B[wb];
            for (int idx = tid; idx < 4096; idx += NTHR) {
                int b = idx >> 6, k4 = idx & 63;
                const float* ga = Ap + (b0base + b) * NH + k4 * 4;
                const float* gb = Bp + (b0base + b) * NH + k4 * 4;
                float4 v0 = __ldcg((const float4*)ga);
                float4 v1 = __ldcg((const float4*)gb);
                int d = b * 64 + (k4 ^ (b & 7));
                h04[d] = v0;
                h14[d] = v1;
            }
        }
        __syncthreads();

        // ---- fused GEMMs via f32x2 (packed along k) ----
        unsigned long long a0p[2][4] = {{0,0,0,0},{0,0,0,0}};
        unsigned long long a1p[2][4] = {{0,0,0,0},{0,0,0,0}};
        const ulonglong2* h0u = (const ulonglong2*)h04;
        const ulonglong2* h1u = (const ulonglong2*)h14;
        const ulonglong2* wu  = (const ulonglong2*)wrow;
#pragma unroll 1
        for (int k4 = 0; k4 < 64; k4++) {
            int ks = k4 ^ sw;
            ulonglong2 h0a = h0u[lane * 64 + ks];
            ulonglong2 h0b = h0u[(lane + 32) * 64 + ks];
            ulonglong2 h1a = h1u[lane * 64 + ks];
            ulonglong2 h1b = h1u[(lane + 32) * 64 + ks];
#pragma unroll
            for (int g = 0; g < 4; g++) {
                ulonglong2 w0 = wu[g * 512 + k4];          // W_hh0 gate g
                ulonglong2 w1 = wu[2048 + g * 512 + k4];   // W_ih1 gate g
                ulonglong2 w2 = wu[4096 + g * 512 + k4];   // W_hh1 gate g
                a0p[0][g] = ffma2(w0.x, h0a.x, a0p[0][g]);
                a0p[0][g] = ffma2(w0.y, h0a.y, a0p[0][g]);
                a0p[1][g] = ffma2(w0.x, h0b.x, a0p[1][g]);
                a0p[1][g] = ffma2(w0.y, h0b.y, a0p[1][g]);
                a1p[0][g] = ffma2(w1.x, h0a.x, a1p[0][g]);
                a1p[0][g] = ffma2(w1.y, h0a.y, a1p[0][g]);
                a1p[0][g] = ffma2(w2.x, h1a.x, a1p[0][g]);
                a1p[0][g] = ffma2(w2.y, h1a.y, a1p[0][g]);
                a1p[1][g] = ffma2(w1.x, h0b.x, a1p[1][g]);
                a1p[1][g] = ffma2(w1.y, h0b.y, a1p[1][g]);
                a1p[1][g] = ffma2(w2.x, h1b.x, a1p[1][g]);
                a1p[1][g] = ffma2(w2.y, h1b.y, a1p[1][g]);
            }
        }

        // ---- layer 0 state update: h0(tick) ----
        if (tick <= NT) {
            float* Aw = g_A[wb];
#pragma unroll
            for (int ch = 0; ch < 2; ch++) {
                int b = b0base + ch * 32 + lane;
                float zi = hsum2(a0p[ch][0]) + bias0[0];
                float zf = hsum2(a0p[ch][1]) + bias0[1];
                float zg = hsum2(a0p[ch][2]) + bias0[2];
                float zo = hsum2(a0p[ch][3]) + bias0[3];
                c0[ch] = sigm(zf) * c0[ch] + sigm(zi) * tanh_f(zg);
                float h = sigm(zo) * tanh_f(c0[ch]);
                __stcg(&Aw[b * NH + j], h);
            }
        }
        // ---- layer 1 state update: h1(tick-1) ----
        if (tick >= 2 && tick <= NT + 1) {
            float* Bw = g_B[rb];
#pragma unroll
            for (int ch = 0; ch < 2; ch++) {
                int b = b0base + ch * 32 + lane;
                float zi = hsum2(a1p[ch][0]) + bias1[0];
                float zf = hsum2(a1p[ch][1]) + bias1[1];
                float zg = hsum2(a1p[ch][2]) + bias1[2];
                float zo = hsum2(a1p[ch][3]) + bias1[3];
                c1[ch] = sigm(zf) * c1[ch] + sigm(zi) * tanh_f(zg);
                float h = sigm(zo) * tanh_f(c1[ch]);
                __stcg(&Bw[b * NH + j], h);
            }
        }
        // ---- output t = tick-3 from the h1 tile (h1(tick-2)) in smem ----
        if (jt == 0 && tick >= 3) {
            int bl = tid >> 2, q = tid & 3, swb = bl & 7;
            float v = 0.f;
#pragma unroll
            for (int i = 0; i < 16; i++) {
                int k4 = q * 16 + i;
                float4 hv = h14[bl * 64 + (k4 ^ swb)];
                float4 wv = *(const float4*)(W_ho + k4 * 4);
                v += hv.x * wv.x + hv.y * wv.y + hv.z * wv.z + hv.w * wv.w;
            }
            v += __shfl_xor_sync(0xffffffffu, v, 1);
            v += __shfl_xor_sync(0xffffffffu, v, 2);
            if (q == 0)
                out[(b0base + bl) * NT + (tick - 3)] = v + bho;
        }

        gridbar(bar += NCTA);
    }
}

extern "C" void kernel_launch(void* const* d_in, const int* in_sizes, int n_in,
                              void* d_out, int out_size)
{
    (void)in_sizes; (void)n_in; (void)out_size;
    cudaFuncSetAttribute(lstm_persist_kernel,
                         cudaFuncAttributeMaxDynamicSharedMemorySize, SMEM_BYTES);
    void* barp = nullptr;
    cudaGetSymbolAddress(&barp, g_arrive);
    cudaMemsetAsync(barp, 0, sizeof(unsigned));

    lstm_persist_kernel<<<NCTA, NTHR, SMEM_BYTES>>>(
        (const float*)d_in[0],   // latent
        (const float*)d_in[1],   // W_lh
        (const float*)d_in[2],   // b_lh
        // d_in[3] = W_ih0 (layer-0 input is all-zero -> unused)
        (const float*)d_in[4],   // W_hh0
        (const float*)d_in[5],   // b_ih0
        (const float*)d_in[6],   // b_hh0
        (const float*)d_in[7],   // W_ih1
        (const float*)d_in[8],   // W_hh1
        (const float*)d_in[9],   // b_ih1
        (const float*)d_in[10],  // b_hh1
        (const float*)d_in[11],  // W_ho
        (const float*)d_in[12],  // b_ho
        (float*)d_out);
}

// round 6
// speedup vs baseline: 2.0386x; 1.9391x over previous
#include <cuda_runtime.h>
#include <cuda_bf16.h>
#include <cstdint>

#define NB 256
#define NH 256
#define NT 512
#define NL 128
#define NCTA 96
#define NTHR 256
#define NTICK (NT + 3)   // 515

// smem byte offsets: A tile 128 rows x 1024B, B tile 64 rows x 1024B
#define OFF_A    0
#define OFF_B    131072
#define ZS_STRIDE 68
#define OFF_ZS   OFF_B                                    // overlays B after MMA
#define OFF_YS   (OFF_B + 128 * ZS_STRIDE * 4)            // after zs
#define SMEM_BYTES (131072 + 65536)                       // 192 KB

// global state
__device__ uint32_t g_H0[2][NB * NH];          // packed (lo<<16)|hi bf16 of h0, [n][k]
__device__ uint32_t g_H1[2][NB * NH];
__device__ float    g_P[2][32][128 * 64];      // layer1 x-partials [buf][pid][r][n]
__device__ float    g_Y[2][8][NB];             // y partials [buf][mu][b]
__device__ unsigned g_arrive;                  // zeroed each launch

// ---------------- helpers ----------------
__device__ __forceinline__ float sigm(float x) {
    return __fdividef(1.0f, 1.0f + __expf(-x));
}
__device__ __forceinline__ float tanh_f(float x) {
    float e = __expf(2.0f * x);
    return 1.0f - __fdividef(2.0f, e + 1.0f);
}
__device__ __forceinline__ uint32_t s2u(const void* p) {
    uint32_t a;
    asm("{.reg .u64 t; cvta.to.shared.u64 t, %1; cvt.u32.u64 %0, t;}" : "=r"(a) : "l"(p));
    return a;
}
// pack two floats into bf16x2 (x low, y high)
__device__ __forceinline__ uint32_t cvt2(float x, float y) {
    uint32_t r;
    asm("cvt.rn.bf16x2.f32 %0, %1, %2;" : "=r"(r) : "f"(y), "f"(x));
    return r;
}
__device__ __forceinline__ float bf_lo(uint32_t u) {
    __nv_bfloat16_raw r; r.x = (unsigned short)(u & 0xffff);
    return __bfloat162float(*(__nv_bfloat16*)&r);
}
__device__ __forceinline__ float bf_hi(uint32_t u) {
    __nv_bfloat16_raw r; r.x = (unsigned short)(u >> 16);
    return __bfloat162float(*(__nv_bfloat16*)&r);
}
__device__ __forceinline__ void split2(float x, float y, uint32_t& hi, uint32_t& lo) {
    hi = cvt2(x, y);
    lo = cvt2(x - bf_lo(hi), y - bf_hi(hi));
}
__device__ __forceinline__ uint32_t packh(float h) {
    uint32_t p = cvt2(h, 0.f);
    uint32_t hb = p & 0xffff;
    float lo = h - bf_lo(p);
    uint32_t l2 = cvt2(lo, 0.f) & 0xffff;
    return (l2 << 16) | hb;
}

__device__ __forceinline__ void ldsm4(uint32_t* r, uint32_t addr) {
    asm volatile("ldmatrix.sync.aligned.m8n8.x4.shared.b16 {%0,%1,%2,%3}, [%4];"
                 : "=r"(r[0]), "=r"(r[1]), "=r"(r[2]), "=r"(r[3]) : "r"(addr));
}
__device__ __forceinline__ void mma16816(float* c, const uint32_t* a, const uint32_t* b) {
    asm volatile(
        "mma.sync.aligned.m16n8k16.row.col.f32.bf16.bf16.f32 "
        "{%0,%1,%2,%3}, {%4,%5,%6,%7}, {%8,%9}, {%0,%1,%2,%3};"
        : "+f"(c[0]), "+f"(c[1]), "+f"(c[2]), "+f"(c[3])
        : "r"(a[0]), "r"(a[1]), "r"(a[2]), "r"(a[3]), "r"(b[0]), "r"(b[1]));
}

__device__ __forceinline__ void gridbar(unsigned target) {
    __threadfence();
    __syncthreads();
    if (threadIdx.x == 0) {
        atomicAdd(&g_arrive, 1u);
        while (*(volatile unsigned*)&g_arrive < target) { }
        __threadfence();
    }
    __syncthreads();
}

__global__ void __launch_bounds__(NTHR, 1)
lstm_mma_kernel(const float* __restrict__ latent,
                const float* __restrict__ W_lh,  const float* __restrict__ b_lh,
                const float* __restrict__ W_hh0, const float* __restrict__ b_ih0,
                const float* __restrict__ b_hh0,
                const float* __restrict__ W_ih1, const float* __restrict__ W_hh1,
                const float* __restrict__ b_ih1, const float* __restrict__ b_hh1,
                const float* __restrict__ W_ho,  const float* __restrict__ b_ho,
                float* __restrict__ out)
{
    extern __shared__ char smem[];
    const uint32_t sbase = s2u(smem);
    const int tid  = threadIdx.x;
    const int warp = tid >> 5;
    const int lane = tid & 31;

    const int bi   = blockIdx.x;
    const int role = bi >> 5;          // 0=hh0, 1=ih1, 2=hh1
    const int pid  = bi & 31;
    const int mu   = pid >> 2;         // unit tile (32 units)
    const int nu   = pid & 3;          // batch tile (64 batches)
    const int nbase = nu * 64;

    // ---- one-time: stage A = [Whi | Wlo] (128 rows x 512 k bf16, swizzled) ----
    {
        const float* Wsrc = (role == 0) ? W_hh0 : (role == 1) ? W_ih1 : W_hh1;
        for (int i = 0; i < 16; i++) {
            int idx = tid + i * 256;           // 0..4095
            int r = idx >> 5, kg = idx & 31;   // row, 8-col group
            int grow = (r & 3) * 256 + mu * 32 + (r >> 2);
            const float4* gp = (const float4*)(Wsrc + grow * 256 + kg * 8);
            float4 f0 = gp[0], f1 = gp[1];
            uint32_t h0, h1, h2, h3, l0, l1, l2, l3;
            split2(f0.x, f0.y, h0, l0);
            split2(f0.z, f0.w, h1, l1);
            split2(f1.x, f1.y, h2, l2);
            split2(f1.z, f1.w, h3, l3);
            int sw = r & 7;
            *(uint4*)(smem + OFF_A + r * 1024 + ((kg ^ sw) << 4))        = make_uint4(h0, h1, h2, h3);
            *(uint4*)(smem + OFF_A + r * 1024 + (((32 + kg) ^ sw) << 4)) = make_uint4(l0, l1, l2, l3);
        }
    }

    // ---- epilogue-thread constants ----
    const int jl  = tid >> 3;          // unit within tile (0..31)
    const int cg8 = tid & 7;           // 8-col group (0..7)
    const int j   = mu * 32 + jl;
    float bias[4] = {0.f, 0.f, 0.f, 0.f};
    if (role == 0) {
#pragma unroll
        for (int g = 0; g < 4; g++) bias[g] = b_ih0[g * NH + j] + b_hh0[g * NH + j];
    } else if (role == 2) {
#pragma unroll
        for (int g = 0; g < 4; g++) bias[g] = b_ih1[g * NH + j] + b_hh1[g * NH + j];
    }
    const float who = W_ho[j];
    const float bho = b_ho[0];

    // ---- init: h_init = latent @ W_lh.T + b_lh (roles 0,2 write h0(0)/h1(0)) ----
    if (role != 1) {
        uint32_t* dst = (role == 0) ? g_H0[0] : g_H1[0];
        for (int i = 0; i < 8; i++) {
            int idx = tid + i * 256;                 // 0..2047
            int jj = mu * 32 + (idx & 31);
            int nn = nbase + (idx >> 5);
            float acc = b_lh[jj];
            for (int k = 0; k < NL; k += 4) {
                float4 lv = *(const float4*)(latent + nn * NL + k);
                float4 wv = *(const float4*)(W_lh + jj * NL + k);
                acc += lv.x * wv.x + lv.y * wv.y + lv.z * wv.z + lv.w * wv.w;
            }
            __stcg(&dst[nn * NH + jj], packh(acc));
        }
    }

    float cst[8];
#pragma unroll
    for (int i = 0; i < 8; i++) cst[i] = 0.f;

    unsigned bar = 0;
    gridbar(bar += NCTA);

    // per-lane ldmatrix address pre-computation
    const int sw   = lane & 7;                         // swizzle key
    const uint32_t aBase = sbase + OFF_A + (uint32_t)(warp * 16 + (lane & 15)) * 1024;
    const int aSel = lane >> 4;
    uint32_t bBase[4];
#pragma unroll
    for (int p = 0; p < 4; p++)
        bBase[p] = sbase + OFF_B + (uint32_t)(p * 16 + ((lane >> 4) << 3) + (lane & 7)) * 1024;
    const int bSel = (lane >> 3) & 1;

    float* zs = (float*)(smem + OFF_ZS);
    float* ys = (float*)(smem + OFF_YS);

    for (int tick = 1; tick <= NTICK; tick++) {
        const bool active = (role == 0) ? (tick <= NT)
                          : (role == 1) ? (tick >= 2 && tick <= NT + 1)
                                        : (tick >= 3 && tick <= NT + 2);

        if (active) {
            // ---- stage B = [hhi | hlo] (64 n-rows x 512 k bf16, swizzled) ----
            {
                const uint32_t* src = (role == 2) ? g_H1[(tick - 1) & 1]
                                                  : g_H0[(tick - 1) & 1];
                for (int i = 0; i < 8; i++) {
                    int idx = tid + i * 256;          // 0..2047
                    int n = idx >> 5, kg = idx & 31;
                    const uint4* gp = (const uint4*)(src + (nbase + n) * NH + kg * 8);
                    uint4 a = __ldcg(gp);
                    uint4 b = __ldcg(gp + 1);
                    uint32_t h0 = __byte_perm(a.x, a.y, 0x5410), h1 = __byte_perm(a.z, a.w, 0x5410);
                    uint32_t h2 = __byte_perm(b.x, b.y, 0x5410), h3 = __byte_perm(b.z, b.w, 0x5410);
                    uint32_t l0 = __byte_perm(a.x, a.y, 0x7632), l1 = __byte_perm(a.z, a.w, 0x7632);
                    uint32_t l2 = __byte_perm(b.x, b.y, 0x7632), l3 = __byte_perm(b.z, b.w, 0x7632);
                    int swn = n & 7;
                    *(uint4*)(smem + OFF_B + n * 1024 + ((kg ^ swn) << 4))        = make_uint4(h0, h1, h2, h3);
                    *(uint4*)(smem + OFF_B + n * 1024 + (((32 + kg) ^ swn) << 4)) = make_uint4(l0, l1, l2, l3);
                }
            }
            __syncthreads();

            // ---- warp MMA: D[16x64] per warp, 3 passes (hh,hl,lh) fused per chunk ----
            float acc[8][4];
#pragma unroll
            for (int nt = 0; nt < 8; nt++)
#pragma unroll
                for (int q = 0; q < 4; q++) acc[nt][q] = 0.f;

#pragma unroll 1
            for (int ca = 0; ca < 16; ca++) {
                const int c0h = 2 * ca;        // hi half byte-chunk base
                const int c0l = 32 + 2 * ca;   // lo half
                uint32_t ah[4], al[4], bh[4][4], bl[4][4];
                ldsm4(ah, aBase + (((c0h + aSel) ^ sw) << 4));
                ldsm4(al, aBase + (((c0l + aSel) ^ sw) << 4));
#pragma unroll
                for (int p = 0; p < 4; p++) {
                    ldsm4(bh[p], bBase[p] + (((c0h + bSel) ^ sw) << 4));
                    ldsm4(bl[p], bBase[p] + (((c0l + bSel) ^ sw) << 4));
                }
#pragma unroll
                for (int nt = 0; nt < 8; nt++) {
                    const uint32_t* bhf = &bh[nt >> 1][(nt & 1) * 2];
                    const uint32_t* blf = &bl[nt >> 1][(nt & 1) * 2];
                    mma16816(acc[nt], ah, bhf);   // Whi * Hhi
                    mma16816(acc[nt], ah, blf);   // Whi * Hlo
                    mma16816(acc[nt], al, bhf);   // Wlo * Hhi
                }
            }
            __syncthreads();   // B reads done before zs overlays B

            const int row0 = warp * 16 + (lane >> 2);
            const int colb = 2 * (lane & 3);

            if (role == 1) {
                // dump layer1 x-partials to global
                float* Pd = g_P[(tick - 1) & 1][pid];
#pragma unroll
                for (int nt = 0; nt < 8; nt++) {
                    int c = nt * 8 + colb;
                    float2 v0 = make_float2(acc[nt][0], acc[nt][1]);
                    float2 v1 = make_float2(acc[nt][2], acc[nt][3]);
                    __stcg((float2*)(Pd + row0 * 64 + c), v0);
                    __stcg((float2*)(Pd + (row0 + 8) * 64 + c), v1);
                }
            } else {
                if (role == 2) {
                    const float* Ps = g_P[tick & 1][pid];
#pragma unroll
                    for (int nt = 0; nt < 8; nt++) {
                        int c = nt * 8 + colb;
                        float2 p0 = __ldcg((const float2*)(Ps + row0 * 64 + c));
                        float2 p1 = __ldcg((const float2*)(Ps + (row0 + 8) * 64 + c));
                        acc[nt][0] += p0.x; acc[nt][1] += p0.y;
                        acc[nt][2] += p1.x; acc[nt][3] += p1.y;
                    }
                }
#pragma unroll
                for (int nt = 0; nt < 8; nt++) {
                    int c = nt * 8 + colb;
                    *(float2*)(zs + row0 * ZS_STRIDE + c)       = make_float2(acc[nt][0], acc[nt][1]);
                    *(float2*)(zs + (row0 + 8) * ZS_STRIDE + c) = make_float2(acc[nt][2], acc[nt][3]);
                }
                __syncthreads();

                // ---- gate nonlinearity + state update (256 threads) ----
                uint32_t* Hd = (role == 0) ? g_H0[tick & 1] : g_H1[tick & 1];
                const int rb = jl * 4;
                float4 zi4a = *(const float4*)(zs + (rb + 0) * ZS_STRIDE + cg8 * 8);
                float4 zi4b = *(const float4*)(zs + (rb + 0) * ZS_STRIDE + cg8 * 8 + 4);
                float4 zf4a = *(const float4*)(zs + (rb + 1) * ZS_STRIDE + cg8 * 8);
                float4 zf4b = *(const float4*)(zs + (rb + 1) * ZS_STRIDE + cg8 * 8 + 4);
                float4 zg4a = *(const float4*)(zs + (rb + 2) * ZS_STRIDE + cg8 * 8);
                float4 zg4b = *(const float4*)(zs + (rb + 2) * ZS_STRIDE + cg8 * 8 + 4);
                float4 zo4a = *(const float4*)(zs + (rb + 3) * ZS_STRIDE + cg8 * 8);
                float4 zo4b = *(const float4*)(zs + (rb + 3) * ZS_STRIDE + cg8 * 8 + 4);
                float ziv[8] = {zi4a.x, zi4a.y, zi4a.z, zi4a.w, zi4b.x, zi4b.y, zi4b.z, zi4b.w};
                float zfv[8] = {zf4a.x, zf4a.y, zf4a.z, zf4a.w, zf4b.x, zf4b.y, zf4b.z, zf4b.w};
                float zgv[8] = {zg4a.x, zg4a.y, zg4a.z, zg4a.w, zg4b.x, zg4b.y, zg4b.z, zg4b.w};
                float zov[8] = {zo4a.x, zo4a.y, zo4a.z, zo4a.w, zo4b.x, zo4b.y, zo4b.z, zo4b.w};
                float yv[8];
#pragma unroll
                for (int c = 0; c < 8; c++) {
                    float zi = ziv[c] + bias[0];
                    float zf = zfv[c] + bias[1];
                    float zg = zgv[c] + bias[2];
                    float zo = zov[c] + bias[3];
                    cst[c] = sigm(zf) * cst[c] + sigm(zi) * tanh_f(zg);
                    float h = sigm(zo) * tanh_f(cst[c]);
                    int col = cg8 * 8 + c;
                    __stcg(&Hd[(nbase + col) * NH + j], packh(h));
                    yv[c] = h * who;
                }
                if (role == 2) {
#pragma unroll
                    for (int c = 0; c < 8; c++)
                        ys[(cg8 * 8 + c) * 33 + jl] = yv[c];
                    __syncthreads();
                    if (tid < 64) {
                        float s = 0.f;
#pragma unroll
                        for (int k = 0; k < 32; k++) s += ys[tid * 33 + k];
                        __stcg(&g_Y[tick & 1][mu][nbase + tid], s);
                    }
                }
            }
        }

        // ---- output summer (role2, mu==0): out col tick-4 ----
        if (role == 2 && mu == 0 && tick >= 4 && tid < 64) {
            float s = bho;
#pragma unroll
            for (int m = 0; m < 8; m++)
                s += __ldcg(&g_Y[(tick - 1) & 1][m][nbase + tid]);
            out[(nbase + tid) * NT + (tick - 4)] = s;
        }

        gridbar(bar += NCTA);
    }
}

extern "C" void kernel_launch(void* const* d_in, const int* in_sizes, int n_in,
                              void* d_out, int out_size)
{
    (void)in_sizes; (void)n_in; (void)out_size;
    cudaFuncSetAttribute(lstm_mma_kernel,
                         cudaFuncAttributeMaxDynamicSharedMemorySize, SMEM_BYTES);
    void* barp = nullptr;
    cudaGetSymbolAddress(&barp, g_arrive);
    cudaMemsetAsync(barp, 0, sizeof(unsigned));

    lstm_mma_kernel<<<NCTA, NTHR, SMEM_BYTES>>>(
        (const float*)d_in[0],   // latent
        (const float*)d_in[1],   // W_lh
        (const float*)d_in[2],   // b_lh
        // d_in[3] = W_ih0 unused (layer-0 input is all-zero)
        (const float*)d_in[4],   // W_hh0
        (const float*)d_in[5],   // b_ih0
        (const float*)d_in[6],   // b_hh0
        (const float*)d_in[7],   // W_ih1
        (const float*)d_in[8],   // W_hh1
        (const float*)d_in[9],   // b_ih1
        (const float*)d_in[10],  // b_hh1
        (const float*)d_in[11],  // W_ho
        (const float*)d_in[12],  // b_ho
        (float*)d_out);
}